// round 9
// baseline (speedup 1.0000x reference)
#include <cuda_runtime.h>
#include <cstdint>

#define NQ      24
#define KTOT    576
#define MSIDE   12
#define MTOT    144
#define CI      16
#define CO      16
#define HID     8
#define BATCH   32
#define DECAYF  1296.0f
#define E_F     2.7182818284590452f
#define NW      88
#define PSTRIDE 64
#define NB      296           // exactly 2 blocks/SM on 148 SMs -> co-resident
#define MAXC    40

// Scratch
__device__ float    g_featT2[KTOT * BATCH * CI];  // [k][c*32+b]
__device__ float    g_Wt[NW * 256];               // [w][pair]
__device__ float4   g_pts[MTOT * PSTRIDE];        // (x0, x1, bump*w, k-as-int)
__device__ int      g_cnt[MTOT];
__device__ unsigned g_bar = 0;                    // monotonic grid barrier

// ---- f32x2 helpers --------------------------------------------------------
__device__ __forceinline__ uint64_t pk2(float lo, float hi) {
    uint64_t r; asm("mov.b64 %0, {%1, %2};" : "=l"(r) : "f"(lo), "f"(hi)); return r;
}
__device__ __forceinline__ void upk2(float& lo, float& hi, uint64_t v) {
    asm("mov.b64 {%0, %1}, %2;" : "=f"(lo), "=f"(hi) : "l"(v));
}
__device__ __forceinline__ uint64_t fma2(uint64_t a, uint64_t b, uint64_t c) {
    uint64_t d; asm("fma.rn.f32x2 %0, %1, %2, %3;" : "=l"(d) : "l"(a), "l"(b), "l"(c)); return d;
}
__device__ __forceinline__ uint64_t mul2(uint64_t a, uint64_t b) {
    uint64_t d; asm("mul.rn.f32x2 %0, %1, %2;" : "=l"(d) : "l"(a), "l"(b)); return d;
}

__device__ __forceinline__ void cp8(uint32_t dst_smem, const void* src) {
    asm volatile("cp.async.ca.shared.global [%0], [%1], 8;\n"
                 :: "r"(dst_smem), "l"(src) : "memory");
}
#define CP_COMMIT() asm volatile("cp.async.commit_group;\n" ::: "memory")
#define CP_WAIT3()  asm volatile("cp.async.wait_group 3;\n" ::: "memory")

// ---------------------------------------------------------------------------
// Single fused kernel: phase A (prep, distributed over the 296 blocks),
// software grid barrier, phase B (main compute).
// ---------------------------------------------------------------------------
__global__ void __launch_bounds__(256, 2)
qc_fused(const float* __restrict__ feats,
         const float* __restrict__ W1,
         const float* __restrict__ W2,
         const float* __restrict__ W3,
         const float* __restrict__ locs,
         const float* __restrict__ qn,
         const float* __restrict__ qw,
         float* __restrict__ out)
{
    const int bid  = blockIdx.x;
    const int t    = threadIdx.x;
    const int lane = t & 31;
    const int o    = t >> 4;
    const int bh   = t & 15;

    __shared__ __align__(16) float  s_f[4][BATCH * CI];   // 4x 2KB feature panels
    __shared__ __align__(16) float4 s_pts[MAXC];
    __shared__ float s_tile[16][33];                       // transpose staging
    __shared__ int   s_pm[MAXC];
    __shared__ int   s_off[MTOT + 1];

    // ===================== Phase A: distributed prep =====================
    // A1: feature transpose. 576 units (b in 0..31, kt in 0..17); block bid<288
    //     handles units 2*bid, 2*bid+1.  featT2[k][c*32+b] = feats[b][c][k]
    if (bid < 288) {
        #pragma unroll
        for (int u = 0; u < 2; u++) {
            const int unit = bid * 2 + u;
            const int b  = unit / 18;
            const int k0 = (unit % 18) * 32;
            {   // read 16c x 32k, coalesced along k
                const int kk = t & 31, c0 = t >> 5;
                #pragma unroll
                for (int c = c0; c < 16; c += 8)
                    s_tile[c][kk] = feats[(b * CI + c) * KTOT + k0 + kk];
            }
            __syncthreads();
            {   // write: 2 passes of (16 kk x 16 c)
                const int c = t & 15;
                const int kk0 = t >> 4;
                #pragma unroll
                for (int kk = kk0; kk < 32; kk += 16)
                    g_featT2[(k0 + kk) * 512 + c * 32 + b] = s_tile[c][kk];
            }
            __syncthreads();
        }
    }
    // A2: weight pack (blocks 0..87), active scan (88..231), zero out (232..295)
    if (bid < 88) {
        const int w = bid, pair = t;
        float v;
        if (w < 16)      v = W1[pair * 16 + w];
        else if (w < 80) { int r = w - 16, g = r >> 3, h = r & 7;
                           v = W2[pair * 64 + h * 8 + g]; }
        else             v = W3[pair * 8 + (w - 80)];
        g_Wt[w * 256 + pair] = v;
    } else if (bid < 88 + MTOT) {
        const int m = bid - 88;
        if (t < 32) {
            const float lx = locs[m * 2 + 0];
            const float ly = locs[m * 2 + 1];
            int cnt = 0;
            for (int base = 0; base < KTOT; base += 32) {
                int k = base + t;
                int i = k / NQ, j = k - i * NQ;
                float x0 = lx - qn[j];
                float x1 = ly - qn[i];
                float r2 = x0 * x0 + x1 * x1;
                float da = DECAYF * r2 * r2;
                bool act = (da < 1.0f);
                unsigned bal = __ballot_sync(0xffffffffu, act);
                if (act) {
                    int pos = cnt + __popc(bal & ((1u << t) - 1u));
                    float bw = E_F * __expf(-1.0f / (1.0f - da)) * (qw[i] * qw[j]);
                    g_pts[m * PSTRIDE + pos] = make_float4(x0, x1, bw, __int_as_float(k));
                }
                cnt += __popc(bal);
            }
            if (t == 0) g_cnt[m] = cnt;
        }
    } else {
        // zero 73728 floats = 18432 float4, 64 blocks x 288
        int base = (bid - 232) * 288;
        ((float4*)out)[base + t] = make_float4(0.f, 0.f, 0.f, 0.f);
        if (t < 32) ((float4*)out)[base + 256 + t] = make_float4(0.f, 0.f, 0.f, 0.f);
    }

    // ===================== Grid barrier (replay-safe) =====================
    __threadfence();
    __syncthreads();
    if (t == 0) {
        unsigned tk = atomicAdd(&g_bar, 1u);
        unsigned target = tk - (tk % NB) + NB;
        while (*(volatile unsigned*)&g_bar < target) { }
    }
    __syncthreads();
    __threadfence();

    // ===================== Phase B: main compute =====================
    // Coalesced weight loads, packed into f32x2 register pairs
    uint64_t w1ap[4], w1bp[4], w2p[4][HID], w3p[4];
    {
        const float* W = g_Wt + t;
        #pragma unroll
        for (int j = 0; j < 4; j++) {
            w1ap[j] = pk2(W[(2 * j) * 256],     W[(2 * j + 1) * 256]);
            w1bp[j] = pk2(W[(8 + 2 * j) * 256], W[(8 + 2 * j + 1) * 256]);
        }
        #pragma unroll
        for (int j = 0; j < 4; j++)
            #pragma unroll
            for (int h = 0; h < HID; h++)
                w2p[j][h] = pk2(W[(16 + (2 * j) * 8 + h) * 256],
                                W[(16 + (2 * j + 1) * 8 + h) * 256]);
        #pragma unroll
        for (int j = 0; j < 4; j++)
            w3p[j] = pk2(W[(80 + 2 * j) * 256], W[(80 + 2 * j + 1) * 256]);
    }

    // Warp 0: exclusive prefix over the 144 active counts
    if (t < 32) {
        int base = t * 5;
        int c0 = (base + 0 < MTOT) ? g_cnt[base + 0] : 0;
        int c1 = (base + 1 < MTOT) ? g_cnt[base + 1] : 0;
        int c2 = (base + 2 < MTOT) ? g_cnt[base + 2] : 0;
        int c3 = (base + 3 < MTOT) ? g_cnt[base + 3] : 0;
        int c4 = (base + 4 < MTOT) ? g_cnt[base + 4] : 0;
        int l0 = c0, l1 = l0 + c1, l2 = l1 + c2, l3 = l2 + c3, l4 = l3 + c4;
        int x = l4;
        #pragma unroll
        for (int d = 1; d < 32; d <<= 1) {
            int y = __shfl_up_sync(0xffffffffu, x, d);
            if (lane >= d) x += y;
        }
        int excl = x - l4;
        if (base + 0 <= MTOT) s_off[base + 0] = excl;
        if (base + 1 <= MTOT) s_off[base + 1] = excl + l0;
        if (base + 2 <= MTOT) s_off[base + 2] = excl + l1;
        if (base + 3 <= MTOT) s_off[base + 3] = excl + l2;
        if (base + 4 <= MTOT) s_off[base + 4] = excl + l3;
    }
    __syncthreads();

    const int T = s_off[MTOT];
    const int chunk = (T + NB - 1) / NB;
    const int p0 = bid * chunk;
    const int n  = min(p0 + chunk, T) - p0;
    if (n <= 0) return;

    if (t < n) {
        int p = p0 + t;
        int lo = 0, hi = MTOT;
        while (hi - lo > 1) { int mid = (lo + hi) >> 1; (s_off[mid] <= p) ? (lo = mid) : (hi = mid); }
        s_pm[t]  = lo;
        s_pts[t] = g_pts[lo * PSTRIDE + (p - s_off[lo])];
    }
    __syncthreads();

    const uint32_t sfb   = (uint32_t)__cvta_generic_to_shared(&s_f[0][0]);
    const uint32_t myoff = (uint32_t)(t * 8);

    #pragma unroll
    for (int j = 0; j < 3; j++) {
        if (j < n)
            cp8(sfb + (uint32_t)j * 2048 + myoff,
                g_featT2 + (size_t)__float_as_int(s_pts[j].w) * 512 + t * 2);
        CP_COMMIT();
    }

    int cm = s_pm[0];
    uint64_t ap = 0;   // packed (a_b0, a_b1)

    for (int i = 0; i < n; i++) {
        if (i + 3 < n)
            cp8(sfb + (uint32_t)((i + 3) & 3) * 2048 + myoff,
                g_featT2 + (size_t)__float_as_int(s_pts[i + 3].w) * 512 + t * 2);
        CP_COMMIT();

        const float4 pt = s_pts[i];
        const int    m  = s_pm[i];
        if (m != cm) {
            float a0, a1; upk2(a0, a1, ap);
            atomicAdd(&out[(2 * bh)     * (CO * MTOT) + o * MTOT + cm], a0);
            atomicAdd(&out[(2 * bh + 1) * (CO * MTOT) + o * MTOT + cm], a1);
            ap = 0; cm = m;
        }
        const float bw = pt.z;
        const uint64_t x0d = pk2(pt.x, pt.x);
        const uint64_t x1d = pk2(pt.y, pt.y);

        // Layer 1: z = x0*w1a + x1*w1b (packed), sin on MUFU
        float h1[HID];
        #pragma unroll
        for (int j = 0; j < 4; j++) {
            uint64_t zp = fma2(x0d, w1ap[j], mul2(x1d, w1bp[j]));
            float z0, z1; upk2(z0, z1, zp);
            h1[2 * j]     = __sinf(z0);
            h1[2 * j + 1] = __sinf(z1);
        }
        // Layer 2: packed over output pairs g
        uint64_t accp[4];
        {
            uint64_t h1d0 = pk2(h1[0], h1[0]);
            #pragma unroll
            for (int j = 0; j < 4; j++) accp[j] = mul2(h1d0, w2p[j][0]);
            #pragma unroll
            for (int h = 1; h < HID; h++) {
                uint64_t h1d = pk2(h1[h], h1[h]);
                #pragma unroll
                for (int j = 0; j < 4; j++) accp[j] = fma2(h1d, w2p[j][h], accp[j]);
            }
        }
        // Layer 3
        float val;
        {
            uint64_t vp = 0;
            #pragma unroll
            for (int j = 0; j < 4; j++) {
                float z0, z1; upk2(z0, z1, accp[j]);
                uint64_t h2p = pk2(__sinf(z0), __sinf(z1));
                vp = fma2(h2p, w3p[j], vp);
            }
            float v0, v1; upk2(v0, v1, vp);
            val = v0 + v1;
        }
        const float v = val * bw;

        CP_WAIT3();
        __syncthreads();

        // Contraction: packed (b0,b1) accumulator; f float2 is already a pair
        const float* fb = &s_f[i & 3][2 * bh];
        #pragma unroll
        for (int cc = 0; cc < CI; cc++) {
            float vv = __shfl_sync(0xffffffffu, v, (lane & 16) + cc);
            uint64_t fpair = *(const uint64_t*)(fb + cc * 32);
            ap = fma2(pk2(vv, vv), fpair, ap);
        }
        __syncthreads();
    }

    {
        float a0, a1; upk2(a0, a1, ap);
        atomicAdd(&out[(2 * bh)     * (CO * MTOT) + o * MTOT + cm], a0);
        atomicAdd(&out[(2 * bh + 1) * (CO * MTOT) + o * MTOT + cm], a1);
    }
}

// ---------------------------------------------------------------------------
extern "C" void kernel_launch(void* const* d_in, const int* in_sizes, int n_in,
                              void* d_out, int out_size) {
    const float* feats = (const float*)d_in[0];  // (32, 16, 576)
    const float* locs  = (const float*)d_in[1];  // (144, 2)
    const float* qn    = (const float*)d_in[2];  // (24,)
    const float* qw    = (const float*)d_in[3];  // (24,)
    const float* W1    = (const float*)d_in[4];  // (16,16,2,8)
    const float* W2    = (const float*)d_in[5];  // (16,16,8,8)
    const float* W3    = (const float*)d_in[6];  // (16,16,8,1)
    float* out = (float*)d_out;                  // (32, 16, 144)

    qc_fused<<<NB, 256>>>(feats, W1, W2, W3, locs, qn, qw, out);
}

// round 10
// speedup vs baseline: 1.1940x; 1.1940x over previous
#include <cuda_runtime.h>
#include <cstdint>

#define NQ      24
#define KTOT    576
#define MSIDE   12
#define MTOT    144
#define CI      16
#define CO      16
#define HID     8
#define BATCH   32
#define DECAYF  1296.0f
#define E_F     2.7182818284590452f
#define NW      88
#define PSTRIDE 64
#define NB      296           // 2 blocks/SM on 148 SMs
#define MAXC    40

// prep block ranges
#define PB_TR   288                  // transpose units: 16 c * 18 k-tiles
#define PB_SCAN (PB_TR + MTOT)       // 288..432
#define PB_W    (PB_SCAN + NW)       // 432..520
#define PB_Z    (PB_W + 72)          // 520..592

// Scratch
__device__ float  g_featT2[KTOT * BATCH * CI];  // [k][c*32+b]
__device__ float  g_Wt[NW * 256];               // [w][pair]
__device__ float4 g_pts[MTOT * PSTRIDE];        // (x0, x1, bump*w, k-as-int)
__device__ int    g_cnt[MTOT];

// ---------------------------------------------------------------------------
// Prep: coalesced-on-both-sides transpose + scan + weight pack + out zero.
// ---------------------------------------------------------------------------
__global__ void qc_prep(const float* __restrict__ feats,
                        const float* __restrict__ W1,
                        const float* __restrict__ W2,
                        const float* __restrict__ W3,
                        const float* __restrict__ locs,
                        const float* __restrict__ qn,
                        const float* __restrict__ qw,
                        float* __restrict__ out) {
    const int bid = blockIdx.x;
    const int t = threadIdx.x;
    if (bid < PB_TR) {
        // One (c, 32-wide k-tile) plane.  Both global accesses coalesced:
        // read fast along k, write fast along b.
        __shared__ float tile[32][33];
        const int c  = bid & 15;
        const int k0 = (bid >> 4) * 32;
        {
            const int kk = t & 31, b0 = t >> 5;
            #pragma unroll
            for (int b = b0; b < 32; b += 8)
                tile[b][kk] = feats[(b * CI + c) * KTOT + k0 + kk];
        }
        __syncthreads();
        {
            const int b = t & 31, kk0 = t >> 5;
            #pragma unroll
            for (int kk = kk0; kk < 32; kk += 8)
                g_featT2[(k0 + kk) * 512 + c * 32 + b] = tile[b][kk];
        }
    } else if (bid < PB_SCAN) {
        // Per-m active scan (warp 0, deterministic ballot compaction)
        const int m = bid - PB_TR;
        if (t < 32) {
            const float lx = locs[m * 2 + 0];
            const float ly = locs[m * 2 + 1];
            int cnt = 0;
            for (int base = 0; base < KTOT; base += 32) {   // 576 = 18*32
                int k = base + t;
                int i = k / NQ, j = k - i * NQ;
                float x0 = lx - qn[j];
                float x1 = ly - qn[i];
                float r2 = x0 * x0 + x1 * x1;
                float da = DECAYF * r2 * r2;
                bool act = (da < 1.0f);
                unsigned bal = __ballot_sync(0xffffffffu, act);
                if (act) {
                    int pos = cnt + __popc(bal & ((1u << t) - 1u));
                    float bw = E_F * __expf(-1.0f / (1.0f - da)) * (qw[i] * qw[j]);
                    g_pts[m * PSTRIDE + pos] = make_float4(x0, x1, bw, __int_as_float(k));
                }
                cnt += __popc(bal);
            }
            if (t == 0) g_cnt[m] = cnt;
        }
    } else if (bid < PB_W) {
        const int w = bid - PB_SCAN;
        const int pair = t;
        float v;
        if (w < 16)      v = W1[pair * 16 + w];
        else if (w < 80) { int r = w - 16, g = r >> 3, h = r & 7;
                           v = W2[pair * 64 + h * 8 + g]; }
        else             v = W3[pair * 8 + (w - 80)];
        g_Wt[w * 256 + pair] = v;
    } else if (bid < PB_Z) {
        int idx = (bid - PB_W) * 256 + t;                  // 18432 float4 slots
        ((float4*)out)[idx] = make_float4(0.f, 0.f, 0.f, 0.f);
    }
}

__device__ __forceinline__ void cp8(uint32_t dst_smem, const void* src) {
    asm volatile("cp.async.ca.shared.global [%0], [%1], 8;\n"
                 :: "r"(dst_smem), "l"(src) : "memory");
}
#define CP_COMMIT() asm volatile("cp.async.commit_group;\n" ::: "memory")
#define CP_WAIT2()  asm volatile("cp.async.wait_group 2;\n" ::: "memory")

// ---------------------------------------------------------------------------
// Main: flat active-list chunks; metadata in smem; 4-deep cp.async feature
// pipeline with ONE barrier per point; sins on MUFU; 4 accumulation chains.
// ---------------------------------------------------------------------------
__global__ void __launch_bounds__(256, 2)
qc_main(float* __restrict__ out) {
    const int t    = threadIdx.x;
    const int lane = t & 31;
    const int o    = t >> 4;
    const int bh   = t & 15;

    __shared__ __align__(16) float  s_f[4][BATCH * CI];   // 4x 2KB feature panels
    __shared__ __align__(16) float4 s_pts[MAXC];
    __shared__ int s_pm[MAXC];
    __shared__ int s_off[MTOT + 1];

    // Coalesced per-thread weight loads (lane == pair)
    float w1a[HID], w1b[HID], w2t[HID][HID], w3[HID];
    {
        const float* W = g_Wt + t;
        #pragma unroll
        for (int h = 0; h < HID; h++) { w1a[h] = W[h * 256]; w1b[h] = W[(8 + h) * 256]; }
        #pragma unroll
        for (int g = 0; g < HID; g++)
            #pragma unroll
            for (int h = 0; h < HID; h++) w2t[g][h] = W[(16 + g * 8 + h) * 256];
        #pragma unroll
        for (int g = 0; g < HID; g++) w3[g] = W[(80 + g) * 256];
    }

    // Warp 0: exclusive prefix over the 144 active counts
    if (t < 32) {
        int base = t * 5;
        int c0 = (base + 0 < MTOT) ? g_cnt[base + 0] : 0;
        int c1 = (base + 1 < MTOT) ? g_cnt[base + 1] : 0;
        int c2 = (base + 2 < MTOT) ? g_cnt[base + 2] : 0;
        int c3 = (base + 3 < MTOT) ? g_cnt[base + 3] : 0;
        int c4 = (base + 4 < MTOT) ? g_cnt[base + 4] : 0;
        int l0 = c0, l1 = l0 + c1, l2 = l1 + c2, l3 = l2 + c3, l4 = l3 + c4;
        int x = l4;
        #pragma unroll
        for (int d = 1; d < 32; d <<= 1) {
            int y = __shfl_up_sync(0xffffffffu, x, d);
            if (lane >= d) x += y;
        }
        int excl = x - l4;
        if (base + 0 <= MTOT) s_off[base + 0] = excl;
        if (base + 1 <= MTOT) s_off[base + 1] = excl + l0;
        if (base + 2 <= MTOT) s_off[base + 2] = excl + l1;
        if (base + 3 <= MTOT) s_off[base + 3] = excl + l2;
        if (base + 4 <= MTOT) s_off[base + 4] = excl + l3;
    }
    __syncthreads();

    const int T = s_off[MTOT];
    const int chunk = (T + NB - 1) / NB;
    const int p0 = blockIdx.x * chunk;
    const int n  = min(p0 + chunk, T) - p0;
    if (n <= 0) return;

    // Preload this block's point metadata (one thread per point)
    if (t < n) {
        int p = p0 + t;
        int lo = 0, hi = MTOT;
        while (hi - lo > 1) { int mid = (lo + hi) >> 1; (s_off[mid] <= p) ? (lo = mid) : (hi = mid); }
        s_pm[t]  = lo;
        s_pts[t] = g_pts[lo * PSTRIDE + (p - s_off[lo])];
    }
    __syncthreads();

    const uint32_t sfb   = (uint32_t)__cvta_generic_to_shared(&s_f[0][0]);
    const uint32_t myoff = (uint32_t)(t * 8);

    // Prefetch points 0..2 (one commit group per point; empty groups kept)
    #pragma unroll
    for (int j = 0; j < 3; j++) {
        if (j < n)
            cp8(sfb + (uint32_t)j * 2048 + myoff,
                g_featT2 + (size_t)__float_as_int(s_pts[j].w) * 512 + t * 2);
        CP_COMMIT();
    }

    int cm = s_pm[0];
    float a0x = 0.f, a0y = 0.f, a1x = 0.f, a1y = 0.f;

    for (int i = 0; i < n; i++) {
        // Group i (issued 3 iters ago) must be done; then one barrier gives
        // (a) cross-thread visibility of panel i, (b) WAR safety for the
        // prefetch below, which clobbers the buffer last read in iter i-1.
        CP_WAIT2();
        __syncthreads();

        if (i + 3 < n)
            cp8(sfb + (uint32_t)((i + 3) & 3) * 2048 + myoff,
                g_featT2 + (size_t)__float_as_int(s_pts[i + 3].w) * 512 + t * 2);
        CP_COMMIT();

        const float4 pt = s_pts[i];
        const int    m  = s_pm[i];
        if (m != cm) {   // flush partials on m transition (rare)
            atomicAdd(&out[(2 * bh)     * (CO * MTOT) + o * MTOT + cm], a0x + a0y);
            atomicAdd(&out[(2 * bh + 1) * (CO * MTOT) + o * MTOT + cm], a1x + a1y);
            a0x = a0y = a1x = a1y = 0.f; cm = m;
        }
        const float x0 = pt.x, x1 = pt.y, bw = pt.z;

        // Tiny MLP: 2 -> 8 (sin) -> 8 (sin) -> 1; sins on MUFU pipe
        float h1[HID];
        #pragma unroll
        for (int h = 0; h < HID; h++)
            h1[h] = __sinf(fmaf(x0, w1a[h], x1 * w1b[h]));
        float val = 0.0f;
        #pragma unroll
        for (int g = 0; g < HID; g++) {
            float acc = 0.0f;
            #pragma unroll
            for (int h = 0; h < HID; h++) acc = fmaf(h1[h], w2t[g][h], acc);
            val = fmaf(__sinf(acc), w3[g], val);
        }
        const float v = val * bw;

        // Contraction: v[o,cc] via intra-warp shuffle; 4 independent chains
        const float* fb = &s_f[i & 3][2 * bh];
        #pragma unroll
        for (int cc = 0; cc < CI; cc += 2) {
            float v0 = __shfl_sync(0xffffffffu, v, (lane & 16) + cc);
            float v1 = __shfl_sync(0xffffffffu, v, (lane & 16) + cc + 1);
            float2 fA = *(const float2*)(fb + cc * 32);
            float2 fB = *(const float2*)(fb + (cc + 1) * 32);
            a0x = fmaf(v0, fA.x, a0x);
            a1x = fmaf(v0, fA.y, a1x);
            a0y = fmaf(v1, fB.x, a0y);
            a1y = fmaf(v1, fB.y, a1y);
        }
    }

    atomicAdd(&out[(2 * bh)     * (CO * MTOT) + o * MTOT + cm], a0x + a0y);
    atomicAdd(&out[(2 * bh + 1) * (CO * MTOT) + o * MTOT + cm], a1x + a1y);
}

// ---------------------------------------------------------------------------
extern "C" void kernel_launch(void* const* d_in, const int* in_sizes, int n_in,
                              void* d_out, int out_size) {
    const float* feats = (const float*)d_in[0];  // (32, 16, 576)
    const float* locs  = (const float*)d_in[1];  // (144, 2)
    const float* qn    = (const float*)d_in[2];  // (24,)
    const float* qw    = (const float*)d_in[3];  // (24,)
    const float* W1    = (const float*)d_in[4];  // (16,16,2,8)
    const float* W2    = (const float*)d_in[5];  // (16,16,8,8)
    const float* W3    = (const float*)d_in[6];  // (16,16,8,1)
    float* out = (float*)d_out;                  // (32, 16, 144)

    qc_prep<<<PB_Z, 256>>>(feats, W1, W2, W3, locs, qn, qw, out);
    qc_main<<<NB, 256>>>(out);
}

// round 11
// speedup vs baseline: 1.1963x; 1.0019x over previous
#include <cuda_runtime.h>
#include <cstdint>

#define NQ      24
#define KTOT    576
#define MSIDE   12
#define MTOT    144
#define CI      16
#define CO      16
#define HID     8
#define BATCH   32
#define DECAYF  1296.0f
#define E_F     2.7182818284590452f
#define NW      88
#define PSTRIDE 64
#define NB      296           // 2 blocks/SM on 148 SMs
#define MAXC    40

// prep block ranges: transpose 288 | scan 18 | weights 11 | zero 9
#define PB_TR   288
#define PB_SCAN (PB_TR + 18)     // 288..306
#define PB_W    (PB_SCAN + 11)   // 306..317
#define PB_Z    (PB_W + 9)       // 317..326

// Scratch
__device__ float  g_featT2[KTOT * BATCH * CI];  // [k][c*32+b]
__device__ float  g_Wt[NW * 256];               // [w][pair]
__device__ float4 g_pts[MTOT * PSTRIDE];        // (x0, x1, bump*w, k-as-int)
__device__ int    g_cnt[MTOT];

// ---------------------------------------------------------------------------
// Prep: transpose (coalesced both sides) + warp-per-m scan + weights + zero.
// ---------------------------------------------------------------------------
__global__ void qc_prep(const float* __restrict__ feats,
                        const float* __restrict__ W1,
                        const float* __restrict__ W2,
                        const float* __restrict__ W3,
                        const float* __restrict__ locs,
                        const float* __restrict__ qn,
                        const float* __restrict__ qw,
                        float* __restrict__ out) {
    const int bid = blockIdx.x;
    const int t = threadIdx.x;
    if (bid < PB_TR) {
        __shared__ float tile[32][33];
        const int c  = bid & 15;
        const int k0 = (bid >> 4) * 32;
        {
            const int kk = t & 31, b0 = t >> 5;
            #pragma unroll
            for (int b = b0; b < 32; b += 8)
                tile[b][kk] = feats[(b * CI + c) * KTOT + k0 + kk];
        }
        __syncthreads();
        {
            const int b = t & 31, kk0 = t >> 5;
            #pragma unroll
            for (int kk = kk0; kk < 32; kk += 8)
                g_featT2[(k0 + kk) * 512 + c * 32 + b] = tile[b][kk];
        }
    } else if (bid < PB_SCAN) {
        // warp-per-m active scan: 18 blocks x 8 warps = 144 m
        const int wid  = t >> 5;
        const int lane = t & 31;
        const int m = (bid - PB_TR) * 8 + wid;
        const float lx = locs[m * 2 + 0];
        const float ly = locs[m * 2 + 1];
        int cnt = 0;
        for (int base = 0; base < KTOT; base += 32) {   // 576 = 18*32
            int k = base + lane;
            int i = k / NQ, j = k - i * NQ;
            float x0 = lx - qn[j];
            float x1 = ly - qn[i];
            float r2 = x0 * x0 + x1 * x1;
            float da = DECAYF * r2 * r2;
            bool act = (da < 1.0f);
            unsigned bal = __ballot_sync(0xffffffffu, act);
            if (act) {
                int pos = cnt + __popc(bal & ((1u << lane) - 1u));
                float bw = E_F * __expf(-1.0f / (1.0f - da)) * (qw[i] * qw[j]);
                g_pts[m * PSTRIDE + pos] = make_float4(x0, x1, bw, __int_as_float(k));
            }
            cnt += __popc(bal);
        }
        if (lane == 0) g_cnt[m] = cnt;
    } else if (bid < PB_W) {
        // weights: 11 blocks x 2048 floats, coalesced stride-256 writes
        int base = (bid - PB_SCAN) * 2048;
        #pragma unroll
        for (int j = 0; j < 8; j++) {
            int idx = base + j * 256 + t;          // < 22528
            int w = idx >> 8, pair = idx & 255;
            float v;
            if (w < 16)      v = W1[pair * 16 + w];
            else if (w < 80) { int r = w - 16, g = r >> 3, h = r & 7;
                               v = W2[pair * 64 + h * 8 + g]; }
            else             v = W3[pair * 8 + (w - 80)];
            g_Wt[idx] = v;
        }
    } else {
        // zero out: 9 blocks x 2048 float4 = 18432 float4 = 73728 floats
        int base = (bid - PB_W) * 2048;
        #pragma unroll
        for (int j = 0; j < 8; j++)
            ((float4*)out)[base + j * 256 + t] = make_float4(0.f, 0.f, 0.f, 0.f);
    }
}

__device__ __forceinline__ void cp8(uint32_t dst_smem, const void* src) {
    asm volatile("cp.async.ca.shared.global [%0], [%1], 8;\n"
                 :: "r"(dst_smem), "l"(src) : "memory");
}
#define CP_COMMIT() asm volatile("cp.async.commit_group;\n" ::: "memory")
#define CP_WAITG3() asm volatile("cp.async.wait_group 3;\n" ::: "memory")

// ---------------------------------------------------------------------------
// Main: deferred contraction — iteration i runs MLP(i) and contraction(i-1)
// as independent streams; 8 panel buffers, barrier every 2 points.
// ---------------------------------------------------------------------------
__global__ void __launch_bounds__(256, 2)
qc_main(float* __restrict__ out) {
    const int t    = threadIdx.x;
    const int lane = t & 31;
    const int o    = t >> 4;
    const int bh   = t & 15;

    __shared__ __align__(16) float  s_f[8][BATCH * CI];   // 8x 2KB feature panels
    __shared__ __align__(16) float4 s_pts[MAXC];
    __shared__ float s_wb[HID * 256];   // w1b in smem (frees regs)
    __shared__ float s_w3[HID * 256];   // w3 in smem
    __shared__ int s_pm[MAXC];
    __shared__ int s_off[MTOT + 1];

    // Weights: w1a + w2 in registers (72), w1b + w3 staged to smem
    float w1a[HID], w2t[HID][HID];
    {
        const float* W = g_Wt + t;
        #pragma unroll
        for (int h = 0; h < HID; h++) {
            w1a[h] = W[h * 256];
            s_wb[h * 256 + t] = W[(8 + h) * 256];
        }
        #pragma unroll
        for (int g = 0; g < HID; g++)
            #pragma unroll
            for (int h = 0; h < HID; h++) w2t[g][h] = W[(16 + g * 8 + h) * 256];
        #pragma unroll
        for (int g = 0; g < HID; g++) s_w3[g * 256 + t] = W[(80 + g) * 256];
    }

    // Warp 0: exclusive prefix over the 144 active counts
    if (t < 32) {
        int base = t * 5;
        int c0 = (base + 0 < MTOT) ? g_cnt[base + 0] : 0;
        int c1 = (base + 1 < MTOT) ? g_cnt[base + 1] : 0;
        int c2 = (base + 2 < MTOT) ? g_cnt[base + 2] : 0;
        int c3 = (base + 3 < MTOT) ? g_cnt[base + 3] : 0;
        int c4 = (base + 4 < MTOT) ? g_cnt[base + 4] : 0;
        int l0 = c0, l1 = l0 + c1, l2 = l1 + c2, l3 = l2 + c3, l4 = l3 + c4;
        int x = l4;
        #pragma unroll
        for (int d = 1; d < 32; d <<= 1) {
            int y = __shfl_up_sync(0xffffffffu, x, d);
            if (lane >= d) x += y;
        }
        int excl = x - l4;
        if (base + 0 <= MTOT) s_off[base + 0] = excl;
        if (base + 1 <= MTOT) s_off[base + 1] = excl + l0;
        if (base + 2 <= MTOT) s_off[base + 2] = excl + l1;
        if (base + 3 <= MTOT) s_off[base + 3] = excl + l2;
        if (base + 4 <= MTOT) s_off[base + 4] = excl + l3;
    }
    __syncthreads();

    const int T = s_off[MTOT];
    const int chunk = (T + NB - 1) / NB;
    const int p0 = blockIdx.x * chunk;
    const int n  = min(p0 + chunk, T) - p0;
    if (n <= 0) return;

    if (t < n) {
        int p = p0 + t;
        int lo = 0, hi = MTOT;
        while (hi - lo > 1) { int mid = (lo + hi) >> 1; (s_off[mid] <= p) ? (lo = mid) : (hi = mid); }
        s_pm[t]  = lo;
        s_pts[t] = g_pts[lo * PSTRIDE + (p - s_off[lo])];
    }
    __syncthreads();

    const uint32_t sfb   = (uint32_t)__cvta_generic_to_shared(&s_f[0][0]);
    const uint32_t myoff = (uint32_t)(t * 8);
    const float* swb = s_wb + t;
    const float* sw3 = s_w3 + t;

    // Prologue: prefetch panels 0..3 (4 commit groups, empty ones kept)
    #pragma unroll
    for (int j = 0; j < 4; j++) {
        if (j < n)
            cp8(sfb + (uint32_t)j * 2048 + myoff,
                g_featT2 + (size_t)__float_as_int(s_pts[j].w) * 512 + t * 2);
        CP_COMMIT();
    }

    int   cm = s_pm[0], m_prev = cm;
    float a0 = 0.f, a1 = 0.f, v_prev = 0.f;

    for (int i = 0; i <= n; i++) {
        // Committed groups so far: 4 + i (panels 0..i+3). <=3 pending after
        // this wait => panels <= i complete. The even-iter barrier then makes
        // them visible block-wide, and provides WAR safety for buffer reuse
        // (panel j read at iter j+1, its buffer rewritten at iter j+4).
        CP_WAITG3();
        if ((i & 1) == 0) __syncthreads();

        if (i + 4 < n)
            cp8(sfb + (uint32_t)((i + 4) & 7) * 2048 + myoff,
                g_featT2 + (size_t)__float_as_int(s_pts[i + 4].w) * 512 + t * 2);
        CP_COMMIT();

        // --- MLP for point i (independent of contraction below) ---
        float v_cur = 0.f;
        int   m_cur = 0;
        if (i < n) {
            const float4 pt = s_pts[i];
            m_cur = s_pm[i];
            const float x0 = pt.x, x1 = pt.y;
            float h1[HID];
            #pragma unroll
            for (int h = 0; h < HID; h++)
                h1[h] = __sinf(fmaf(x0, w1a[h], x1 * swb[h * 256]));
            float val = 0.0f;
            #pragma unroll
            for (int g = 0; g < HID; g++) {
                float acc = 0.0f;
                #pragma unroll
                for (int h = 0; h < HID; h++) acc = fmaf(h1[h], w2t[g][h], acc);
                val = fmaf(__sinf(acc), sw3[g * 256], val);
            }
            v_cur = val * pt.z;
        }

        // --- Contraction for point i-1 (uses v_prev; overlaps MLP above) ---
        if (i >= 1) {
            if (m_prev != cm) {   // rare m transition: flush
                atomicAdd(&out[(2 * bh)     * (CO * MTOT) + o * MTOT + cm], a0);
                atomicAdd(&out[(2 * bh + 1) * (CO * MTOT) + o * MTOT + cm], a1);
                a0 = 0.f; a1 = 0.f; cm = m_prev;
            }
            const float* fb = &s_f[(i - 1) & 7][2 * bh];
            #pragma unroll
            for (int cc = 0; cc < CI; cc++) {
                float vv = __shfl_sync(0xffffffffu, v_prev, (lane & 16) + cc);
                float2 f = *(const float2*)(fb + cc * 32);
                a0 = fmaf(vv, f.x, a0);
                a1 = fmaf(vv, f.y, a1);
            }
        }

        v_prev = v_cur;
        m_prev = m_cur;
    }

    atomicAdd(&out[(2 * bh)     * (CO * MTOT) + o * MTOT + cm], a0);
    atomicAdd(&out[(2 * bh + 1) * (CO * MTOT) + o * MTOT + cm], a1);
}

// ---------------------------------------------------------------------------
extern "C" void kernel_launch(void* const* d_in, const int* in_sizes, int n_in,
                              void* d_out, int out_size) {
    const float* feats = (const float*)d_in[0];  // (32, 16, 576)
    const float* locs  = (const float*)d_in[1];  // (144, 2)
    const float* qn    = (const float*)d_in[2];  // (24,)
    const float* qw    = (const float*)d_in[3];  // (24,)
    const float* W1    = (const float*)d_in[4];  // (16,16,2,8)
    const float* W2    = (const float*)d_in[5];  // (16,16,8,8)
    const float* W3    = (const float*)d_in[6];  // (16,16,8,1)
    float* out = (float*)d_out;                  // (32, 16, 144)

    qc_prep<<<PB_Z, 256>>>(feats, W1, W2, W3, locs, qn, qw, out);
    qc_main<<<NB, 256>>>(out);
}

// round 12
// speedup vs baseline: 1.1985x; 1.0019x over previous
#include <cuda_runtime.h>
#include <cstdint>

#define NQ      24
#define KTOT    576
#define MSIDE   12
#define MTOT    144
#define CI      16
#define CO      16
#define HID     8
#define BATCH   32
#define DECAYF  1296.0f
#define E_F     2.7182818284590452f
#define NW      88
#define PSTRIDE 64
#define NB      296           // 2 blocks/SM on 148 SMs
#define MAXC    40

// prep block ranges: transpose 288 | scan 18 | weights 11 | zero 9
#define PB_TR   288
#define PB_SCAN (PB_TR + 18)
#define PB_W    (PB_SCAN + 11)
#define PB_Z    (PB_W + 9)

// Scratch
__device__ float  g_featT2[KTOT * BATCH * CI];  // [k][c*32+b]
__device__ float  g_Wt[NW * 256];               // [w][pair]
__device__ float4 g_pts[MTOT * PSTRIDE];        // (x0, x1, bump*w, k-as-int)
__device__ int    g_cnt[MTOT];

// ---- f32x2 helpers --------------------------------------------------------
__device__ __forceinline__ uint64_t pk2(float lo, float hi) {
    uint64_t r; asm("mov.b64 %0, {%1, %2};" : "=l"(r) : "f"(lo), "f"(hi)); return r;
}
__device__ __forceinline__ void upk2(float& lo, float& hi, uint64_t v) {
    asm("mov.b64 {%0, %1}, %2;" : "=f"(lo), "=f"(hi) : "l"(v));
}
__device__ __forceinline__ uint64_t fma2(uint64_t a, uint64_t b, uint64_t c) {
    uint64_t d; asm("fma.rn.f32x2 %0, %1, %2, %3;" : "=l"(d) : "l"(a), "l"(b), "l"(c)); return d;
}
__device__ __forceinline__ uint64_t mul2(uint64_t a, uint64_t b) {
    uint64_t d; asm("mul.rn.f32x2 %0, %1, %2;" : "=l"(d) : "l"(a), "l"(b)); return d;
}

// ---------------------------------------------------------------------------
// Prep (unchanged from R11): transpose + warp-per-m scan + weights + zero.
// ---------------------------------------------------------------------------
__global__ void qc_prep(const float* __restrict__ feats,
                        const float* __restrict__ W1,
                        const float* __restrict__ W2,
                        const float* __restrict__ W3,
                        const float* __restrict__ locs,
                        const float* __restrict__ qn,
                        const float* __restrict__ qw,
                        float* __restrict__ out) {
    const int bid = blockIdx.x;
    const int t = threadIdx.x;
    if (bid < PB_TR) {
        __shared__ float tile[32][33];
        const int c  = bid & 15;
        const int k0 = (bid >> 4) * 32;
        {
            const int kk = t & 31, b0 = t >> 5;
            #pragma unroll
            for (int b = b0; b < 32; b += 8)
                tile[b][kk] = feats[(b * CI + c) * KTOT + k0 + kk];
        }
        __syncthreads();
        {
            const int b = t & 31, kk0 = t >> 5;
            #pragma unroll
            for (int kk = kk0; kk < 32; kk += 8)
                g_featT2[(k0 + kk) * 512 + c * 32 + b] = tile[b][kk];
        }
    } else if (bid < PB_SCAN) {
        const int wid  = t >> 5;
        const int lane = t & 31;
        const int m = (bid - PB_TR) * 8 + wid;
        const float lx = locs[m * 2 + 0];
        const float ly = locs[m * 2 + 1];
        int cnt = 0;
        for (int base = 0; base < KTOT; base += 32) {
            int k = base + lane;
            int i = k / NQ, j = k - i * NQ;
            float x0 = lx - qn[j];
            float x1 = ly - qn[i];
            float r2 = x0 * x0 + x1 * x1;
            float da = DECAYF * r2 * r2;
            bool act = (da < 1.0f);
            unsigned bal = __ballot_sync(0xffffffffu, act);
            if (act) {
                int pos = cnt + __popc(bal & ((1u << lane) - 1u));
                float bw = E_F * __expf(-1.0f / (1.0f - da)) * (qw[i] * qw[j]);
                g_pts[m * PSTRIDE + pos] = make_float4(x0, x1, bw, __int_as_float(k));
            }
            cnt += __popc(bal);
        }
        if (lane == 0) g_cnt[m] = cnt;
    } else if (bid < PB_W) {
        int base = (bid - PB_SCAN) * 2048;
        #pragma unroll
        for (int j = 0; j < 8; j++) {
            int idx = base + j * 256 + t;
            int w = idx >> 8, pair = idx & 255;
            float v;
            if (w < 16)      v = W1[pair * 16 + w];
            else if (w < 80) { int r = w - 16, g = r >> 3, h = r & 7;
                               v = W2[pair * 64 + h * 8 + g]; }
            else             v = W3[pair * 8 + (w - 80)];
            g_Wt[idx] = v;
        }
    } else {
        int base = (bid - PB_W) * 2048;
        #pragma unroll
        for (int j = 0; j < 8; j++)
            ((float4*)out)[base + j * 256 + t] = make_float4(0.f, 0.f, 0.f, 0.f);
    }
}

__device__ __forceinline__ void cp8(uint32_t dst_smem, const void* src) {
    asm volatile("cp.async.ca.shared.global [%0], [%1], 8;\n"
                 :: "r"(dst_smem), "l"(src) : "memory");
}
#define CP_COMMIT() asm volatile("cp.async.commit_group;\n" ::: "memory")
#define CP_WAIT3()  asm volatile("cp.async.wait_group 3;\n" ::: "memory")

// ---------------------------------------------------------------------------
// Main: exact R8 loop structure; arithmetic switched to packed f32x2.
// ---------------------------------------------------------------------------
__global__ void __launch_bounds__(256, 2)
qc_main(float* __restrict__ out) {
    const int t    = threadIdx.x;
    const int lane = t & 31;
    const int o    = t >> 4;
    const int bh   = t & 15;

    __shared__ __align__(16) float  s_f[4][BATCH * CI];   // 4x 2KB feature panels
    __shared__ __align__(16) float4 s_pts[MAXC];
    __shared__ int s_pm[MAXC];
    __shared__ int s_off[MTOT + 1];

    // Coalesced weight loads, packed into f32x2 register pairs
    uint64_t w1ap[4], w1bp[4], w2p[4][HID], w3p[4];
    {
        const float* W = g_Wt + t;
        #pragma unroll
        for (int j = 0; j < 4; j++) {
            w1ap[j] = pk2(W[(2 * j) * 256],     W[(2 * j + 1) * 256]);
            w1bp[j] = pk2(W[(8 + 2 * j) * 256], W[(8 + 2 * j + 1) * 256]);
        }
        #pragma unroll
        for (int j = 0; j < 4; j++)
            #pragma unroll
            for (int h = 0; h < HID; h++)
                w2p[j][h] = pk2(W[(16 + (2 * j) * 8 + h) * 256],
                                W[(16 + (2 * j + 1) * 8 + h) * 256]);
        #pragma unroll
        for (int j = 0; j < 4; j++)
            w3p[j] = pk2(W[(80 + 2 * j) * 256], W[(80 + 2 * j + 1) * 256]);
    }

    // Warp 0: exclusive prefix over the 144 active counts
    if (t < 32) {
        int base = t * 5;
        int c0 = (base + 0 < MTOT) ? g_cnt[base + 0] : 0;
        int c1 = (base + 1 < MTOT) ? g_cnt[base + 1] : 0;
        int c2 = (base + 2 < MTOT) ? g_cnt[base + 2] : 0;
        int c3 = (base + 3 < MTOT) ? g_cnt[base + 3] : 0;
        int c4 = (base + 4 < MTOT) ? g_cnt[base + 4] : 0;
        int l0 = c0, l1 = l0 + c1, l2 = l1 + c2, l3 = l2 + c3, l4 = l3 + c4;
        int x = l4;
        #pragma unroll
        for (int d = 1; d < 32; d <<= 1) {
            int y = __shfl_up_sync(0xffffffffu, x, d);
            if (lane >= d) x += y;
        }
        int excl = x - l4;
        if (base + 0 <= MTOT) s_off[base + 0] = excl;
        if (base + 1 <= MTOT) s_off[base + 1] = excl + l0;
        if (base + 2 <= MTOT) s_off[base + 2] = excl + l1;
        if (base + 3 <= MTOT) s_off[base + 3] = excl + l2;
        if (base + 4 <= MTOT) s_off[base + 4] = excl + l3;
    }
    __syncthreads();

    const int T = s_off[MTOT];
    const int chunk = (T + NB - 1) / NB;
    const int p0 = blockIdx.x * chunk;
    const int n  = min(p0 + chunk, T) - p0;
    if (n <= 0) return;

    // Preload this block's point metadata (one thread per point)
    if (t < n) {
        int p = p0 + t;
        int lo = 0, hi = MTOT;
        while (hi - lo > 1) { int mid = (lo + hi) >> 1; (s_off[mid] <= p) ? (lo = mid) : (hi = mid); }
        s_pm[t]  = lo;
        s_pts[t] = g_pts[lo * PSTRIDE + (p - s_off[lo])];
    }
    __syncthreads();

    const uint32_t sfb   = (uint32_t)__cvta_generic_to_shared(&s_f[0][0]);
    const uint32_t myoff = (uint32_t)(t * 8);

    // Prefetch points 0..2 (one commit group per point; empty groups kept)
    #pragma unroll
    for (int j = 0; j < 3; j++) {
        if (j < n)
            cp8(sfb + (uint32_t)j * 2048 + myoff,
                g_featT2 + (size_t)__float_as_int(s_pts[j].w) * 512 + t * 2);
        CP_COMMIT();
    }

    int cm = s_pm[0];
    uint64_t ap = 0;   // packed (a_b0, a_b1)

    for (int i = 0; i < n; i++) {
        if (i + 3 < n)
            cp8(sfb + (uint32_t)((i + 3) & 3) * 2048 + myoff,
                g_featT2 + (size_t)__float_as_int(s_pts[i + 3].w) * 512 + t * 2);
        CP_COMMIT();

        const float4 pt = s_pts[i];
        const int    m  = s_pm[i];
        if (m != cm) {
            float a0, a1; upk2(a0, a1, ap);
            atomicAdd(&out[(2 * bh)     * (CO * MTOT) + o * MTOT + cm], a0);
            atomicAdd(&out[(2 * bh + 1) * (CO * MTOT) + o * MTOT + cm], a1);
            ap = 0; cm = m;
        }
        const float bw = pt.z;
        const uint64_t x0d = pk2(pt.x, pt.x);
        const uint64_t x1d = pk2(pt.y, pt.y);

        // Layer 1: z = x0*w1a + x1*w1b (packed), sins on MUFU
        float h1[HID];
        #pragma unroll
        for (int j = 0; j < 4; j++) {
            uint64_t zp = fma2(x0d, w1ap[j], mul2(x1d, w1bp[j]));
            float z0, z1; upk2(z0, z1, zp);
            h1[2 * j]     = __sinf(z0);
            h1[2 * j + 1] = __sinf(z1);
        }
        // Layer 2: packed over output pairs g
        uint64_t accp[4];
        {
            uint64_t h1d0 = pk2(h1[0], h1[0]);
            #pragma unroll
            for (int j = 0; j < 4; j++) accp[j] = mul2(h1d0, w2p[j][0]);
            #pragma unroll
            for (int h = 1; h < HID; h++) {
                uint64_t h1d = pk2(h1[h], h1[h]);
                #pragma unroll
                for (int j = 0; j < 4; j++) accp[j] = fma2(h1d, w2p[j][h], accp[j]);
            }
        }
        // Layer 3
        float val;
        {
            uint64_t vp = 0;
            #pragma unroll
            for (int j = 0; j < 4; j++) {
                float z0, z1; upk2(z0, z1, accp[j]);
                uint64_t h2p = pk2(__sinf(z0), __sinf(z1));
                vp = fma2(h2p, w3p[j], vp);
            }
            float v0, v1; upk2(v0, v1, vp);
            val = v0 + v1;
        }
        const float v = val * bw;

        CP_WAIT3();           // group i complete (<=3 newer pending)
        __syncthreads();      // panel i visible block-wide

        // Contraction: packed (b0,b1) accumulator; float2 panel is the pair
        const float* fb = &s_f[i & 3][2 * bh];
        #pragma unroll
        for (int cc = 0; cc < CI; cc++) {
            float vv = __shfl_sync(0xffffffffu, v, (lane & 16) + cc);
            uint64_t fpair = *(const uint64_t*)(fb + cc * 32);
            ap = fma2(pk2(vv, vv), fpair, ap);
        }
        __syncthreads();      // reads done before next iteration's clobber
    }

    {
        float a0, a1; upk2(a0, a1, ap);
        atomicAdd(&out[(2 * bh)     * (CO * MTOT) + o * MTOT + cm], a0);
        atomicAdd(&out[(2 * bh + 1) * (CO * MTOT) + o * MTOT + cm], a1);
    }
}

// ---------------------------------------------------------------------------
extern "C" void kernel_launch(void* const* d_in, const int* in_sizes, int n_in,
                              void* d_out, int out_size) {
    const float* feats = (const float*)d_in[0];  // (32, 16, 576)
    const float* locs  = (const float*)d_in[1];  // (144, 2)
    const float* qn    = (const float*)d_in[2];  // (24,)
    const float* qw    = (const float*)d_in[3];  // (24,)
    const float* W1    = (const float*)d_in[4];  // (16,16,2,8)
    const float* W2    = (const float*)d_in[5];  // (16,16,8,8)
    const float* W3    = (const float*)d_in[6];  // (16,16,8,1)
    float* out = (float*)d_out;                  // (32, 16, 144)

    qc_prep<<<PB_Z, 256>>>(feats, W1, W2, W3, locs, qn, qw, out);
    qc_main<<<NB, 256>>>(out);
}